// round 2
// baseline (speedup 1.0000x reference)
#include <cuda_runtime.h>
#include <cuda_bf16.h>

// Problem constants
#define CDIM 512
#define NSEG 640         // S
#define PPP  250         // points per segment
#define NB   32          // BO
#define NERF 147         // 7 + 7*10*2

// Scratch (allocation-free rule: __device__ globals)
__device__ float g_ctr [NSEG*3];     // rotated mean point + trans, per segment
__device__ float g_th  [NB*CDIM];    // silu hidden of timestep MLP
__device__ float g_temb[NB*CDIM];    // final timestep embedding
__device__ float g_X   [NSEG*CDIM];  // pooled mean features (640 x 512)
__device__ float g_Y1  [NSEG*256];
__device__ float g_H1  [NSEG*256];
__device__ float g_Y2  [NSEG*128];
__device__ float g_H2  [NSEG*128];

// ---------------------------------------------------------------------------
// K1: per-segment mean of part_pcs, then quat rotate + translate.
// Segments are contiguous: rows [s*250, (s+1)*250). 96 threads (mult of 3)
// so each thread accumulates a fixed xyz component with coalesced loads.
// ---------------------------------------------------------------------------
__global__ void k_seg(const float* __restrict__ noise,
                      const float* __restrict__ pcs,
                      const int*   __restrict__ blen)
{
    int s = blockIdx.x, tid = threadIdx.x;
    const float* base = pcs + (long)s * (PPP*3);
    float acc = 0.f;
    for (int j = tid; j < PPP*3; j += 96) acc += base[j];
    __shared__ float sh[96];
    sh[tid] = acc;
    __syncthreads();
    if (tid == 0) {
        float m0=0.f, m1=0.f, m2=0.f;
        #pragma unroll
        for (int k = 0; k < 96; k += 3) { m0 += sh[k]; m1 += sh[k+1]; m2 += sh[k+2]; }
        float inv = 1.f / (float)blen[s];
        float px = m0*inv, py = m1*inv, pz = m2*inv;
        float qw = noise[s*7+3], qx = noise[s*7+4], qy = noise[s*7+5], qz = noise[s*7+6];
        float rn = rsqrtf(qw*qw + qx*qx + qy*qy + qz*qz);
        qw*=rn; qx*=rn; qy*=rn; qz*=rn;
        float tx = 2.f*(qy*pz - qz*py);
        float ty = 2.f*(qz*px - qx*pz);
        float tz = 2.f*(qx*py - qy*px);
        g_ctr[s*3+0] = px + qw*tx + (qy*tz - qz*ty) + noise[s*7+0];
        g_ctr[s*3+1] = py + qw*ty + (qz*tx - qx*tz) + noise[s*7+1];
        g_ctr[s*3+2] = pz + qw*tz + (qx*ty - qy*tx) + noise[s*7+2];
    }
}

// ---------------------------------------------------------------------------
// K2a: timestep embedding (cos|sin, 512) -> @t_w1 + t_b1 -> silu  (32 x 512)
// grid (4, 4): 8 rows x 128 cols per block, K = 512
// ---------------------------------------------------------------------------
__global__ void k_temb1(const int* __restrict__ ts,
                        const float* __restrict__ W,
                        const float* __restrict__ B)
{
    __shared__ float E[8][CDIM];
    int r0 = blockIdx.x * 8;
    int c  = blockIdx.y * 128 + threadIdx.x;
    for (int idx = threadIdx.x; idx < 8*CDIM; idx += 128) {
        int r = idx >> 9, k = idx & 511;
        float t = (float)ts[r0 + r];
        int j = k & 255;
        float f = expf(-9.210340371976184f * (float)j * (1.f/256.f));
        float a = t * f;
        E[r][k] = (k < 256) ? cosf(a) : sinf(a);
    }
    __syncthreads();
    float bb = B[c];
    float acc[8];
    #pragma unroll
    for (int r = 0; r < 8; r++) acc[r] = bb;
    for (int k = 0; k < CDIM; k++) {
        float w = W[k*CDIM + c];
        #pragma unroll
        for (int r = 0; r < 8; r++) acc[r] = fmaf(E[r][k], w, acc[r]);
    }
    #pragma unroll
    for (int r = 0; r < 8; r++) {
        float x = acc[r];
        g_th[(r0+r)*CDIM + c] = x / (1.f + expf(-x));
    }
}

// K2b: g_temb = g_th @ t_w2 + t_b2   (32 x 512), grid (4,4)
__global__ void k_temb2(const float* __restrict__ W,
                        const float* __restrict__ B)
{
    __shared__ float Hs[8][CDIM];
    int r0 = blockIdx.x * 8;
    int c  = blockIdx.y * 128 + threadIdx.x;
    for (int idx = threadIdx.x; idx < 8*(CDIM/4); idx += 128) {
        int r = idx >> 7, q = idx & 127;
        ((float4*)Hs[r])[q] = ((const float4*)(g_th + (r0+r)*CDIM))[q];
    }
    __syncthreads();
    float bb = B[c];
    float acc[8];
    #pragma unroll
    for (int r = 0; r < 8; r++) acc[r] = bb;
    for (int k = 0; k < CDIM; k++) {
        float w = W[k*CDIM + c];
        #pragma unroll
        for (int r = 0; r < 8; r++) acc[r] = fmaf(Hs[r][k], w, acc[r]);
    }
    #pragma unroll
    for (int r = 0; r < 8; r++) g_temb[(r0+r)*CDIM + c] = acc[r];
}

// ---------------------------------------------------------------------------
// K3: build X[s][c] = nerf_embed(noise[s]) @ pfc_w + pfc_b
//                   + ctr[s] . pe_w[:,c] + pe_b[c] + temb[s/20][c]
// grid (80, 4): 8 rows x 128 cols, K = 147
// nerf layout: [x(7) | f-major (sin(7) then cos(7)) x 10 freqs]
// ---------------------------------------------------------------------------
__global__ void k_X(const float* __restrict__ noise,
                    const float* __restrict__ PFW,
                    const float* __restrict__ PFB,
                    const float* __restrict__ PEW,
                    const float* __restrict__ PEB)
{
    __shared__ float E[8][NERF+1];
    int r0 = blockIdx.x * 8;
    int c  = blockIdx.y * 128 + threadIdx.x;
    for (int idx = threadIdx.x; idx < 8*NERF; idx += 128) {
        int r = idx / NERF;
        int j = idx - r * NERF;
        int s = r0 + r;
        float v;
        if (j < 7) {
            v = noise[s*7 + j];
        } else {
            int jj = j - 7;
            int f  = jj / 14;
            int rr = jj - f*14;
            float x = noise[s*7 + (rr < 7 ? rr : rr-7)];
            float a = x * exp2f((float)f);
            v = (rr < 7) ? sinf(a) : cosf(a);
        }
        E[r][j] = v;
    }
    __syncthreads();
    float bb = PFB[c];
    float acc[8];
    #pragma unroll
    for (int r = 0; r < 8; r++) acc[r] = bb;
    for (int k = 0; k < NERF; k++) {
        float w = PFW[k*CDIM + c];
        #pragma unroll
        for (int r = 0; r < 8; r++) acc[r] = fmaf(E[r][k], w, acc[r]);
    }
    float w0 = PEW[c], w1 = PEW[CDIM + c], w2 = PEW[2*CDIM + c], pb = PEB[c];
    #pragma unroll
    for (int r = 0; r < 8; r++) {
        int s = r0 + r;
        float v = acc[r] + pb
                + g_ctr[s*3+0]*w0 + g_ctr[s*3+1]*w1 + g_ctr[s*3+2]*w2
                + g_temb[(s/20)*CDIM + c];
        g_X[s*CDIM + c] = v;
    }
}

// ---------------------------------------------------------------------------
// K4: Y1 = X @ o_w1 + o_b1   (640x512 @ 512x256), grid (80, 2)
// ---------------------------------------------------------------------------
__global__ void k_gemm1(const float* __restrict__ W,
                        const float* __restrict__ B)
{
    __shared__ float Xs[8][CDIM];
    int r0 = blockIdx.x * 8;
    int c  = blockIdx.y * 128 + threadIdx.x;
    for (int idx = threadIdx.x; idx < 8*(CDIM/4); idx += 128) {
        int r = idx >> 7, q = idx & 127;
        ((float4*)Xs[r])[q] = ((const float4*)(g_X + (r0+r)*CDIM))[q];
    }
    __syncthreads();
    float bb = B[c];
    float acc[8];
    #pragma unroll
    for (int r = 0; r < 8; r++) acc[r] = bb;
    for (int k = 0; k < CDIM; k++) {
        float w = W[k*256 + c];
        #pragma unroll
        for (int r = 0; r < 8; r++) acc[r] = fmaf(Xs[r][k], w, acc[r]);
    }
    #pragma unroll
    for (int r = 0; r < 8; r++) g_Y1[(r0+r)*256 + c] = acc[r];
}

// K6: Y2 = H1 @ o_w2 + o_b2  (640x256 @ 256x128), grid (80)
__global__ void k_gemm2(const float* __restrict__ W,
                        const float* __restrict__ B)
{
    __shared__ float Hs[8][256];
    int r0 = blockIdx.x * 8;
    int c  = threadIdx.x;  // 128
    for (int idx = threadIdx.x; idx < 8*64; idx += 128) {
        int r = idx >> 6, q = idx & 63;
        ((float4*)Hs[r])[q] = ((const float4*)(g_H1 + (r0+r)*256))[q];
    }
    __syncthreads();
    float bb = B[c];
    float acc[8];
    #pragma unroll
    for (int r = 0; r < 8; r++) acc[r] = bb;
    for (int k = 0; k < 256; k++) {
        float w = W[k*128 + c];
        #pragma unroll
        for (int r = 0; r < 8; r++) acc[r] = fmaf(Hs[r][k], w, acc[r]);
    }
    #pragma unroll
    for (int r = 0; r < 8; r++) g_Y2[(r0+r)*128 + c] = acc[r];
}

// ---------------------------------------------------------------------------
// BN + ReLU over axis 0 (640 rows). Block = 32 cols x 8 row-warps (coalesced).
// Population variance (ddof=0), eps 1e-5, matching jnp.var + rsqrt.
// ---------------------------------------------------------------------------
template <int NC>
__global__ void k_bn(const float* __restrict__ G,
                     const float* __restrict__ Bp)
{
    const float* Y = (NC == 256) ? g_Y1 : g_Y2;
    float*       H = (NC == 256) ? g_H1 : g_H2;
    int lane = threadIdx.x & 31;
    int ry   = threadIdx.x >> 5;     // 0..7
    int c    = blockIdx.x * 32 + lane;
    float s1 = 0.f, s2 = 0.f;
    for (int r = ry; r < NSEG; r += 8) {
        float v = Y[r*NC + c];
        s1 += v; s2 += v*v;
    }
    __shared__ float sh1[8][32], sh2[8][32];
    sh1[ry][lane] = s1; sh2[ry][lane] = s2;
    __syncthreads();
    if (ry == 0) {
        #pragma unroll
        for (int k = 1; k < 8; k++) { s1 += sh1[k][lane]; s2 += sh2[k][lane]; }
        float m   = s1 * (1.f/NSEG);
        float var = s2 * (1.f/NSEG) - m*m;
        float sc  = rsqrtf(var + 1e-5f) * G[c];
        sh1[0][lane] = sc;
        sh2[0][lane] = Bp[c] - m*sc;
    }
    __syncthreads();
    float sc = sh1[0][lane], sb = sh2[0][lane];
    for (int r = ry; r < NSEG; r += 8) {
        float v = Y[r*NC + c] * sc + sb;
        H[r*NC + c] = fmaxf(v, 0.f);
    }
}

// ---------------------------------------------------------------------------
// K8: out = H2 @ o_w3 + o_b3  (640x128 @ 128x7). One block per row;
// warp j (j<7) computes out[s][j] by warp-reduced dot over 128.
// ---------------------------------------------------------------------------
__global__ void k_out(const float* __restrict__ W3,
                      const float* __restrict__ B3,
                      float* __restrict__ out)
{
    int s = blockIdx.x;
    __shared__ float h[128];
    if (threadIdx.x < 128) h[threadIdx.x] = g_H2[s*128 + threadIdx.x];
    __syncthreads();
    int w = threadIdx.x >> 5, lane = threadIdx.x & 31;
    if (w < 7) {
        float acc = 0.f;
        for (int k = lane; k < 128; k += 32) acc += h[k] * W3[k*7 + w];
        #pragma unroll
        for (int o = 16; o; o >>= 1) acc += __shfl_down_sync(0xffffffffu, acc, o);
        if (lane == 0) out[s*7 + w] = acc + B3[w];
    }
}

// ---------------------------------------------------------------------------
extern "C" void kernel_launch(void* const* d_in, const int* in_sizes, int n_in,
                              void* d_out, int out_size)
{
    const float* noise = (const float*)d_in[0];
    const int*   ts    = (const int*)  d_in[1];
    const float* pcs   = (const float*)d_in[2];
    // d_in[3] = segment_ids (arange/PPP — contiguity exploited), unused
    const int*   blen  = (const int*)  d_in[4];
    const float* pew   = (const float*)d_in[5];
    const float* peb   = (const float*)d_in[6];
    const float* tw1   = (const float*)d_in[7];
    const float* tb1   = (const float*)d_in[8];
    const float* tw2   = (const float*)d_in[9];
    const float* tb2   = (const float*)d_in[10];
    const float* pfw   = (const float*)d_in[11];
    const float* pfb   = (const float*)d_in[12];
    const float* ow1   = (const float*)d_in[13];
    const float* ob1   = (const float*)d_in[14];
    const float* bn1g  = (const float*)d_in[15];
    const float* bn1b  = (const float*)d_in[16];
    const float* ow2   = (const float*)d_in[17];
    const float* ob2   = (const float*)d_in[18];
    const float* bn2g  = (const float*)d_in[19];
    const float* bn2b  = (const float*)d_in[20];
    const float* ow3   = (const float*)d_in[21];
    const float* ob3   = (const float*)d_in[22];
    float* out = (float*)d_out;

    k_seg  <<<NSEG, 96>>>(noise, pcs, blen);
    k_temb1<<<dim3(4,4), 128>>>(ts, tw1, tb1);
    k_temb2<<<dim3(4,4), 128>>>(tw2, tb2);
    k_X    <<<dim3(80,4), 128>>>(noise, pfw, pfb, pew, peb);
    k_gemm1<<<dim3(80,2), 128>>>(ow1, ob1);
    k_bn<256><<<8, 256>>>(bn1g, bn1b);
    k_gemm2<<<80, 128>>>(ow2, ob2);
    k_bn<128><<<4, 256>>>(bn2g, bn2b);
    k_out  <<<NSEG, 256>>>(ow3, ob3, out);
}

// round 6
// speedup vs baseline: 1.9881x; 1.9881x over previous
#include <cuda_runtime.h>
#include <cuda_bf16.h>

// Problem constants
#define CDIM 512
#define NSEG 640         // S
#define PPP  250         // points per segment
#define NB   32          // BO
#define NERF 147         // 7 + 7*10*2

// Scratch (__device__ globals; allocation-free rule)
__device__ float g_ctr  [NSEG*3];      // rotated mean point + trans
__device__ float g_nerf [NSEG*NERF];   // nerf embedding rows
__device__ float g_E32  [NB*CDIM];     // raw timestep embedding
__device__ float g_th   [NB*CDIM];     // silu hidden
__device__ float g_temb [NB*CDIM];     // final timestep embedding
__device__ float g_X    [NSEG*CDIM];   // pooled mean features
__device__ float g_Y1   [NSEG*256];
__device__ float g_Y2   [NSEG*128];
// BN stats: [0,256) sum1 | [256,512) sumsq1 | [512,640) sum2 | [640,768) sumsq2
__device__ float g_stats[768];

// ---------------------------------------------------------------------------
// K0 prep: blocks 0..639  -> segment mean + quat rotate + nerf row
//          blocks 640..643 -> raw timestep embedding rows, block 640 zeros stats
// ---------------------------------------------------------------------------
__global__ void k_pre(const float* __restrict__ noise,
                      const int*   __restrict__ ts,
                      const float* __restrict__ pcs,
                      const int*   __restrict__ blen)
{
    int bid = blockIdx.x, tid = threadIdx.x;
    if (bid < NSEG) {
        __shared__ float sh[192];
        __shared__ float shn[8];
        int s = bid;
        if (tid < 7) shn[tid] = noise[s*7 + tid];
        const float* base = pcs + (long)s * (PPP*3);
        float a = 0.f;
        for (int j = tid; j < PPP*3; j += 192) a += base[j];   // 192%3==0: fixed comp
        sh[tid] = a;
        __syncthreads();
        if (tid < 3) {
            float m = 0.f;
            for (int k = tid; k < 192; k += 3) m += sh[k];
            sh[tid] = m;
        }
        __syncthreads();
        if (tid == 0) {
            float inv = 1.f / (float)blen[s];
            float px = sh[0]*inv, py = sh[1]*inv, pz = sh[2]*inv;
            float qw = shn[3], qx = shn[4], qy = shn[5], qz = shn[6];
            float rn = rsqrtf(qw*qw + qx*qx + qy*qy + qz*qz);
            qw*=rn; qx*=rn; qy*=rn; qz*=rn;
            float tx = 2.f*(qy*pz - qz*py);
            float ty = 2.f*(qz*px - qx*pz);
            float tz = 2.f*(qx*py - qy*px);
            g_ctr[s*3+0] = px + qw*tx + (qy*tz - qz*ty) + shn[0];
            g_ctr[s*3+1] = py + qw*ty + (qz*tx - qx*tz) + shn[1];
            g_ctr[s*3+2] = pz + qw*tz + (qx*ty - qy*tx) + shn[2];
        }
        if (tid < NERF) {
            float v;
            if (tid < 7) v = shn[tid];
            else {
                int jj = tid - 7;
                int f  = jj / 14;
                int rr = jj - f*14;
                float x = shn[rr < 7 ? rr : rr-7];
                float arg = x * (float)(1 << f);
                v = (rr < 7) ? sinf(arg) : cosf(arg);
            }
            g_nerf[s*NERF + tid] = v;
        }
    } else {
        int b2 = bid - NSEG;                 // 0..3, 8 rows each
        for (int idx = tid; idx < 8*CDIM; idx += 192) {
            int r = idx >> 9, k = idx & 511;
            float t = (float)ts[b2*8 + r];
            int j = k & 255;
            float f = expf(-9.210340371976184f * (float)j * (1.0f/256.0f));
            float a = t * f;
            g_E32[(b2*8 + r)*CDIM + k] = (k < 256) ? cosf(a) : sinf(a);
        }
        if (b2 == 0)
            for (int i = tid; i < 768; i += 192) g_stats[i] = 0.f;
    }
}

// ---------------------------------------------------------------------------
// 32x512 @ 512x512 MLP layer. grid (4 rowblk, 16 colblk), block 128.
// 8 rows x 32 cols per block; K=512 split across 4 warps (128 each).
// STAGE 0: g_E32 -> silu -> g_th.  STAGE 1: g_th -> g_temb.
// Global buffers bound in DEVICE code (host cannot take __device__ addresses).
// ---------------------------------------------------------------------------
template<int STAGE>
__global__ void k_mlp512(const float* __restrict__ W,
                         const float* __restrict__ B)
{
    const float* Ein = (STAGE == 0) ? g_E32 : g_th;
    float*       Out = (STAGE == 0) ? g_th  : g_temb;
    __shared__ float Es[8][CDIM];
    __shared__ float ps[3][8][32];
    int tid = threadIdx.x;
    int lane = tid & 31, ks = tid >> 5;
    int r0 = blockIdx.x * 8;
    int c  = blockIdx.y * 32 + lane;
    for (int idx = tid; idx < 8*128; idx += 128) {
        int r = idx >> 7, q = idx & 127;
        ((float4*)Es[r])[q] = ((const float4*)(Ein + (r0+r)*CDIM))[q];
    }
    __syncthreads();
    int kbase = ks * 128;
    const float* Wp = W + (long)kbase * CDIM + c;
    float acc[8];
    #pragma unroll
    for (int r = 0; r < 8; r++) acc[r] = 0.f;
    for (int k0 = 0; k0 < 128; k0 += 8) {
        float w[8];
        #pragma unroll
        for (int u = 0; u < 8; u++) w[u] = Wp[(long)(k0+u)*CDIM];
        #pragma unroll
        for (int r = 0; r < 8; r++) {
            float4 e0 = *(const float4*)&Es[r][kbase + k0];
            float4 e1 = *(const float4*)&Es[r][kbase + k0 + 4];
            acc[r] = fmaf(e0.x, w[0], acc[r]);
            acc[r] = fmaf(e0.y, w[1], acc[r]);
            acc[r] = fmaf(e0.z, w[2], acc[r]);
            acc[r] = fmaf(e0.w, w[3], acc[r]);
            acc[r] = fmaf(e1.x, w[4], acc[r]);
            acc[r] = fmaf(e1.y, w[5], acc[r]);
            acc[r] = fmaf(e1.z, w[6], acc[r]);
            acc[r] = fmaf(e1.w, w[7], acc[r]);
        }
    }
    if (ks > 0) {
        #pragma unroll
        for (int r = 0; r < 8; r++) ps[ks-1][r][lane] = acc[r];
    }
    __syncthreads();
    if (ks == 0) {
        float bb = B[c];
        #pragma unroll
        for (int r = 0; r < 8; r++) {
            float v = acc[r] + ps[0][r][lane] + ps[1][r][lane] + ps[2][r][lane] + bb;
            if (STAGE == 0) v = v / (1.f + expf(-v));
            Out[(r0+r)*CDIM + c] = v;
        }
    }
}

// ---------------------------------------------------------------------------
// K3: X[s][c] = nerf[s] @ pfc_w + pfc_b + ctr[s].pe_w[:,c] + pe_b + temb[s/20][c]
// grid (40, 4), block 128: 16 rows x 128 cols, K = 147
// ---------------------------------------------------------------------------
__global__ void k_X(const float* __restrict__ PFW, const float* __restrict__ PFB,
                    const float* __restrict__ PEW, const float* __restrict__ PEB)
{
    __shared__ float En[16][NERF+1];     // row stride 148 floats (16B multiple)
    int tid = threadIdx.x;
    int r0 = blockIdx.x * 16;
    int c  = blockIdx.y * 128 + tid;
    for (int idx = tid; idx < 16*NERF; idx += 128) {
        int r = idx / NERF, j = idx - r*NERF;
        En[r][j] = g_nerf[(r0+r)*NERF + j];
    }
    if (tid < 16) En[tid][NERF] = 0.f;
    __syncthreads();
    float acc[16];
    #pragma unroll
    for (int r = 0; r < 16; r++) acc[r] = 0.f;
    const float* Wp = PFW + c;
    for (int k0 = 0; k0 < 144; k0 += 8) {
        float w[8];
        #pragma unroll
        for (int u = 0; u < 8; u++) w[u] = Wp[(k0+u)*CDIM];
        #pragma unroll
        for (int r = 0; r < 16; r++) {
            float4 e0 = *(const float4*)&En[r][k0];
            float4 e1 = *(const float4*)&En[r][k0+4];
            acc[r] = fmaf(e0.x, w[0], acc[r]);
            acc[r] = fmaf(e0.y, w[1], acc[r]);
            acc[r] = fmaf(e0.z, w[2], acc[r]);
            acc[r] = fmaf(e0.w, w[3], acc[r]);
            acc[r] = fmaf(e1.x, w[4], acc[r]);
            acc[r] = fmaf(e1.y, w[5], acc[r]);
            acc[r] = fmaf(e1.z, w[6], acc[r]);
            acc[r] = fmaf(e1.w, w[7], acc[r]);
        }
    }
    {   // tail k = 144..146
        float w0 = Wp[144*CDIM], w1 = Wp[145*CDIM], w2 = Wp[146*CDIM];
        #pragma unroll
        for (int r = 0; r < 16; r++) {
            acc[r] = fmaf(En[r][144], w0, acc[r]);
            acc[r] = fmaf(En[r][145], w1, acc[r]);
            acc[r] = fmaf(En[r][146], w2, acc[r]);
        }
    }
    float pw0 = PEW[c], pw1 = PEW[CDIM + c], pw2 = PEW[2*CDIM + c];
    float pb  = PEB[c] + PFB[c];
    #pragma unroll
    for (int r = 0; r < 16; r++) {
        int s = r0 + r;
        float v = acc[r] + pb
                + g_ctr[s*3+0]*pw0 + g_ctr[s*3+1]*pw1 + g_ctr[s*3+2]*pw2
                + g_temb[(s/20)*CDIM + c];
        g_X[s*CDIM + c] = v;
    }
}

// ---------------------------------------------------------------------------
// K4: Y1 = X @ o_w1 + o_b1 (640x512x256) + per-column stat atomics.
// grid (40, 2), block 256: 16 rows x 128 cols, 2-way split-K (256 each)
// ---------------------------------------------------------------------------
__global__ void k_gemm1(const float* __restrict__ W, const float* __restrict__ B)
{
    __shared__ float Xs[16][CDIM];     // 32 KB
    __shared__ float red[16][128];     // 8 KB
    int tid = threadIdx.x;
    int cl = tid & 127, ks = tid >> 7;
    int r0 = blockIdx.x * 16;
    int c  = blockIdx.y * 128 + cl;
    for (int idx = tid; idx < 16*128; idx += 256) {
        int r = idx >> 7, q = idx & 127;
        ((float4*)Xs[r])[q] = ((const float4*)(g_X + (r0+r)*CDIM))[q];
    }
    __syncthreads();
    int kbase = ks * 256;
    const float* Wp = W + (long)kbase * 256 + c;
    float acc[16];
    #pragma unroll
    for (int r = 0; r < 16; r++) acc[r] = 0.f;
    for (int k0 = 0; k0 < 256; k0 += 8) {
        float w[8];
        #pragma unroll
        for (int u = 0; u < 8; u++) w[u] = Wp[(long)(k0+u)*256];
        #pragma unroll
        for (int r = 0; r < 16; r++) {
            float4 e0 = *(const float4*)&Xs[r][kbase + k0];
            float4 e1 = *(const float4*)&Xs[r][kbase + k0 + 4];
            acc[r] = fmaf(e0.x, w[0], acc[r]);
            acc[r] = fmaf(e0.y, w[1], acc[r]);
            acc[r] = fmaf(e0.z, w[2], acc[r]);
            acc[r] = fmaf(e0.w, w[3], acc[r]);
            acc[r] = fmaf(e1.x, w[4], acc[r]);
            acc[r] = fmaf(e1.y, w[5], acc[r]);
            acc[r] = fmaf(e1.z, w[6], acc[r]);
            acc[r] = fmaf(e1.w, w[7], acc[r]);
        }
    }
    if (ks == 1) {
        #pragma unroll
        for (int r = 0; r < 16; r++) red[r][cl] = acc[r];
    }
    __syncthreads();
    if (ks == 0) {
        float bb = B[c];
        float s1 = 0.f, s2 = 0.f;
        #pragma unroll
        for (int r = 0; r < 16; r++) {
            float y = acc[r] + red[r][cl] + bb;
            g_Y1[(r0+r)*256 + c] = y;
            s1 += y; s2 += y*y;
        }
        atomicAdd(&g_stats[c], s1);
        atomicAdd(&g_stats[256 + c], s2);
    }
}

// ---------------------------------------------------------------------------
// K5: H1 = relu(bn1(Y1)) applied on load; Y2 = H1 @ o_w2 + o_b2 + stat atomics.
// grid (40), block 256: 16 rows x 128 cols, 2-way split-K (128 each)
// ---------------------------------------------------------------------------
__global__ void k_gemm2(const float* __restrict__ W, const float* __restrict__ B,
                        const float* __restrict__ G1, const float* __restrict__ B1)
{
    __shared__ float Hs[16][256];      // 16 KB
    __shared__ float red[16][128];
    __shared__ float sc[256], sb[256];
    int tid = threadIdx.x;
    {
        float m = g_stats[tid]       * (1.f/NSEG);
        float v = g_stats[256 + tid] * (1.f/NSEG) - m*m;
        float s = rsqrtf(v + 1e-5f) * G1[tid];
        sc[tid] = s; sb[tid] = B1[tid] - m*s;
    }
    __syncthreads();
    int r0 = blockIdx.x * 16;
    for (int idx = tid; idx < 16*256; idx += 256) {
        int r = idx >> 8, j = idx & 255;
        float y = g_Y1[(r0+r)*256 + j];
        Hs[r][j] = fmaxf(fmaf(y, sc[j], sb[j]), 0.f);
    }
    __syncthreads();
    int cl = tid & 127, ks = tid >> 7;
    int kbase = ks * 128;
    const float* Wp = W + (long)kbase * 128 + cl;
    float acc[16];
    #pragma unroll
    for (int r = 0; r < 16; r++) acc[r] = 0.f;
    for (int k0 = 0; k0 < 128; k0 += 8) {
        float w[8];
        #pragma unroll
        for (int u = 0; u < 8; u++) w[u] = Wp[(long)(k0+u)*128];
        #pragma unroll
        for (int r = 0; r < 16; r++) {
            float4 e0 = *(const float4*)&Hs[r][kbase + k0];
            float4 e1 = *(const float4*)&Hs[r][kbase + k0 + 4];
            acc[r] = fmaf(e0.x, w[0], acc[r]);
            acc[r] = fmaf(e0.y, w[1], acc[r]);
            acc[r] = fmaf(e0.z, w[2], acc[r]);
            acc[r] = fmaf(e0.w, w[3], acc[r]);
            acc[r] = fmaf(e1.x, w[4], acc[r]);
            acc[r] = fmaf(e1.y, w[5], acc[r]);
            acc[r] = fmaf(e1.z, w[6], acc[r]);
            acc[r] = fmaf(e1.w, w[7], acc[r]);
        }
    }
    if (ks == 1) {
        #pragma unroll
        for (int r = 0; r < 16; r++) red[r][cl] = acc[r];
    }
    __syncthreads();
    if (ks == 0) {
        float bb = B[cl];
        float s1 = 0.f, s2 = 0.f;
        #pragma unroll
        for (int r = 0; r < 16; r++) {
            float y = acc[r] + red[r][cl] + bb;
            g_Y2[(r0+r)*128 + cl] = y;
            s1 += y; s2 += y*y;
        }
        atomicAdd(&g_stats[512 + cl], s1);
        atomicAdd(&g_stats[640 + cl], s2);
    }
}

// ---------------------------------------------------------------------------
// K6: out = relu(bn2(Y2)) @ o_w3 + o_b3.  grid (80), block 256: 8 segs/block.
// ---------------------------------------------------------------------------
__global__ void k_out(const float* __restrict__ W3, const float* __restrict__ B3,
                      const float* __restrict__ G2, const float* __restrict__ B2c,
                      float* __restrict__ out)
{
    __shared__ float sc[128], sb[128];
    __shared__ float h[8][128];
    __shared__ float w3[128*7];
    __shared__ float b3[7];
    int tid = threadIdx.x;
    if (tid < 128) {
        float m = g_stats[512 + tid] * (1.f/NSEG);
        float v = g_stats[640 + tid] * (1.f/NSEG) - m*m;
        float s = rsqrtf(v + 1e-5f) * G2[tid];
        sc[tid] = s; sb[tid] = B2c[tid] - m*s;
    }
    for (int idx = tid; idx < 128*7; idx += 256) w3[idx] = W3[idx];
    if (tid < 7) b3[tid] = B3[tid];
    __syncthreads();
    int r0 = blockIdx.x * 8;
    for (int idx = tid; idx < 8*128; idx += 256) {
        int r = idx >> 7, j = idx & 127;
        float y = g_Y2[(r0+r)*128 + j];
        h[r][j] = fmaxf(fmaf(y, sc[j], sb[j]), 0.f);
    }
    __syncthreads();
    int wid = tid >> 5, lane = tid & 31;
    float hv[4];
    #pragma unroll
    for (int u = 0; u < 4; u++) hv[u] = h[wid][lane + u*32];
    #pragma unroll
    for (int j = 0; j < 7; j++) {
        float a = 0.f;
        #pragma unroll
        for (int u = 0; u < 4; u++) a = fmaf(hv[u], w3[(lane + u*32)*7 + j], a);
        #pragma unroll
        for (int o = 16; o; o >>= 1) a += __shfl_down_sync(0xffffffffu, a, o);
        if (lane == 0) out[(r0+wid)*7 + j] = a + b3[j];
    }
}

// ---------------------------------------------------------------------------
extern "C" void kernel_launch(void* const* d_in, const int* in_sizes, int n_in,
                              void* d_out, int out_size)
{
    const float* noise = (const float*)d_in[0];
    const int*   ts    = (const int*)  d_in[1];
    const float* pcs   = (const float*)d_in[2];
    const int*   blen  = (const int*)  d_in[4];
    const float* pew   = (const float*)d_in[5];
    const float* peb   = (const float*)d_in[6];
    const float* tw1   = (const float*)d_in[7];
    const float* tb1   = (const float*)d_in[8];
    const float* tw2   = (const float*)d_in[9];
    const float* tb2   = (const float*)d_in[10];
    const float* pfw   = (const float*)d_in[11];
    const float* pfb   = (const float*)d_in[12];
    const float* ow1   = (const float*)d_in[13];
    const float* ob1   = (const float*)d_in[14];
    const float* bn1g  = (const float*)d_in[15];
    const float* bn1b  = (const float*)d_in[16];
    const float* ow2   = (const float*)d_in[17];
    const float* ob2   = (const float*)d_in[18];
    const float* bn2g  = (const float*)d_in[19];
    const float* bn2b  = (const float*)d_in[20];
    const float* ow3   = (const float*)d_in[21];
    const float* ob3   = (const float*)d_in[22];
    float* out = (float*)d_out;

    k_pre       <<<NSEG + 4, 192>>>(noise, ts, pcs, blen);
    k_mlp512<0> <<<dim3(4,16), 128>>>(tw1, tb1);
    k_mlp512<1> <<<dim3(4,16), 128>>>(tw2, tb2);
    k_X         <<<dim3(40,4), 128>>>(pfw, pfb, pew, peb);
    k_gemm1     <<<dim3(40,2), 256>>>(ow1, ob1);
    k_gemm2     <<<40, 256>>>(ow2, ob2, bn1g, bn1b);
    k_out       <<<80, 256>>>(ow3, ob3, bn2g, bn2b, out);
}

// round 9
// speedup vs baseline: 2.7695x; 1.3931x over previous
#include <cuda_runtime.h>
#include <cuda_bf16.h>

// Problem constants
#define CDIM 512
#define NSEG 640         // S
#define PPP  250         // points per segment
#define NB   32          // BO
#define NERF 147         // 7 + 7*10*2

// Scratch (__device__ globals; allocation-free rule)
__device__ float g_ctr  [NSEG*3];
__device__ float g_nerf [NSEG*NERF];
__device__ float g_E32  [NB*CDIM];
__device__ float g_th   [NB*CDIM];
__device__ float g_temb [NB*CDIM];
__device__ float g_X    [NSEG*CDIM];
__device__ float g_Y1   [NSEG*256];
__device__ float g_Y2   [NSEG*128];
// BN stats: [0,256) sum1 | [256,512) sumsq1 | [512,640) sum2 | [640,768) sumsq2
__device__ float g_stats[768];

// ---------------------------------------------------------------------------
// K0 prep: blocks 0..639 -> segment mean + quat rotate + nerf row
//          blocks 640..643 -> raw timestep embedding; block 640 zeros stats
// ---------------------------------------------------------------------------
__global__ void k_pre(const float* __restrict__ noise,
                      const int*   __restrict__ ts,
                      const float* __restrict__ pcs,
                      const int*   __restrict__ blen)
{
    int bid = blockIdx.x, tid = threadIdx.x;
    if (bid < NSEG) {
        __shared__ float sh[192];
        __shared__ float shn[8];
        int s = bid;
        if (tid < 7) shn[tid] = noise[s*7 + tid];
        const float* base = pcs + (long)s * (PPP*3);
        float a = 0.f;
        for (int j = tid; j < PPP*3; j += 192) a += base[j];
        sh[tid] = a;
        __syncthreads();
        if (tid < 3) {
            float m = 0.f;
            for (int k = tid; k < 192; k += 3) m += sh[k];
            sh[tid] = m;
        }
        __syncthreads();
        if (tid == 0) {
            float inv = 1.f / (float)blen[s];
            float px = sh[0]*inv, py = sh[1]*inv, pz = sh[2]*inv;
            float qw = shn[3], qx = shn[4], qy = shn[5], qz = shn[6];
            float rn = rsqrtf(qw*qw + qx*qx + qy*qy + qz*qz);
            qw*=rn; qx*=rn; qy*=rn; qz*=rn;
            float tx = 2.f*(qy*pz - qz*py);
            float ty = 2.f*(qz*px - qx*pz);
            float tz = 2.f*(qx*py - qy*px);
            g_ctr[s*3+0] = px + qw*tx + (qy*tz - qz*ty) + shn[0];
            g_ctr[s*3+1] = py + qw*ty + (qz*tx - qx*tz) + shn[1];
            g_ctr[s*3+2] = pz + qw*tz + (qx*ty - qy*tx) + shn[2];
        }
        if (tid < NERF) {
            float v;
            if (tid < 7) v = shn[tid];
            else {
                int jj = tid - 7;
                int f  = jj / 14;
                int rr = jj - f*14;
                float x = shn[rr < 7 ? rr : rr-7];
                float arg = x * (float)(1 << f);
                v = (rr < 7) ? sinf(arg) : cosf(arg);
            }
            g_nerf[s*NERF + tid] = v;
        }
    } else {
        int b2 = bid - NSEG;
        for (int idx = tid; idx < 8*CDIM; idx += 192) {
            int r = idx >> 9, k = idx & 511;
            float t = (float)ts[b2*8 + r];
            int j = k & 255;
            float f = expf(-9.210340371976184f * (float)j * (1.0f/256.0f));
            float a = t * f;
            g_E32[(b2*8 + r)*CDIM + k] = (k < 256) ? cosf(a) : sinf(a);
        }
        if (b2 == 0)
            for (int i = tid; i < 768; i += 192) g_stats[i] = 0.f;
    }
}

// ---------------------------------------------------------------------------
// 32x512 @ 512x512 MLP. grid (4,16), block 256: 8 rows x 32 cols,
// K=512 split 8 ways (64 each) -> 8 warps/block for latency coverage.
// STAGE 0: g_E32 -> silu -> g_th.  STAGE 1: g_th -> g_temb.
// ---------------------------------------------------------------------------
template<int STAGE>
__global__ void k_mlp512(const float* __restrict__ W,
                         const float* __restrict__ B)
{
    const float* Ein = (STAGE == 0) ? g_E32 : g_th;
    float*       Out = (STAGE == 0) ? g_th  : g_temb;
    __shared__ float Es[8][CDIM];          // 16 KB
    __shared__ float ps[7][8][32];         // 7 KB
    int tid = threadIdx.x;
    int lane = tid & 31, ks = tid >> 5;    // 0..7
    int r0 = blockIdx.x * 8;
    int c  = blockIdx.y * 32 + lane;
    for (int idx = tid; idx < 8*128; idx += 256) {
        int r = idx >> 7, q = idx & 127;
        ((float4*)Es[r])[q] = ((const float4*)(Ein + (r0+r)*CDIM))[q];
    }
    __syncthreads();
    int kbase = ks * 64;
    const float* Wp = W + (long)kbase * CDIM + c;
    float acc[8];
    #pragma unroll
    for (int r = 0; r < 8; r++) acc[r] = 0.f;
    for (int k0 = 0; k0 < 64; k0 += 8) {
        float w[8];
        #pragma unroll
        for (int u = 0; u < 8; u++) w[u] = Wp[(long)(k0+u)*CDIM];
        #pragma unroll
        for (int r = 0; r < 8; r++) {
            float4 e0 = *(const float4*)&Es[r][kbase + k0];
            float4 e1 = *(const float4*)&Es[r][kbase + k0 + 4];
            acc[r] = fmaf(e0.x, w[0], acc[r]);
            acc[r] = fmaf(e0.y, w[1], acc[r]);
            acc[r] = fmaf(e0.z, w[2], acc[r]);
            acc[r] = fmaf(e0.w, w[3], acc[r]);
            acc[r] = fmaf(e1.x, w[4], acc[r]);
            acc[r] = fmaf(e1.y, w[5], acc[r]);
            acc[r] = fmaf(e1.z, w[6], acc[r]);
            acc[r] = fmaf(e1.w, w[7], acc[r]);
        }
    }
    if (ks > 0) {
        #pragma unroll
        for (int r = 0; r < 8; r++) ps[ks-1][r][lane] = acc[r];
    }
    __syncthreads();
    if (ks == 0) {
        float bb = B[c];
        #pragma unroll
        for (int r = 0; r < 8; r++) {
            float v = acc[r] + bb;
            #pragma unroll
            for (int u = 0; u < 7; u++) v += ps[u][r][lane];
            if (STAGE == 0) v = v / (1.f + expf(-v));
            Out[(r0+r)*CDIM + c] = v;
        }
    }
}

// ---------------------------------------------------------------------------
// K3: X[s][c] = nerf[s] @ pfc_w + pfc_b + ctr[s].pe_w[:,c] + pe_b + temb[s/20][c]
// grid (80,4), block 256: 8 rows x 128 cols, K=147 split 72/75 across 2 halves.
// ---------------------------------------------------------------------------
__global__ void k_X(const float* __restrict__ PFW, const float* __restrict__ PFB,
                    const float* __restrict__ PEW, const float* __restrict__ PEB)
{
    __shared__ float En[8][NERF+1];      // row stride 148
    __shared__ float red[8][128];
    int tid = threadIdx.x;
    int cl = tid & 127, ks = tid >> 7;   // 0/1
    int r0 = blockIdx.x * 8;
    int c  = blockIdx.y * 128 + cl;
    for (int idx = tid; idx < 8*NERF; idx += 256) {
        int r = idx / NERF, j = idx - r*NERF;
        En[r][j] = g_nerf[(r0+r)*NERF + j];
    }
    __syncthreads();
    float acc[8];
    #pragma unroll
    for (int r = 0; r < 8; r++) acc[r] = 0.f;
    const float* Wp = PFW + c;
    int kbeg = ks ? 72 : 0;
    int kend = ks ? 144 : 72;            // ks1 also takes tail 144..146
    for (int k0 = kbeg; k0 < kend; k0 += 8) {
        float w[8];
        #pragma unroll
        for (int u = 0; u < 8; u++) w[u] = Wp[(k0+u)*CDIM];
        #pragma unroll
        for (int r = 0; r < 8; r++) {
            float4 e0 = *(const float4*)&En[r][k0];
            float4 e1 = *(const float4*)&En[r][k0+4];
            acc[r] = fmaf(e0.x, w[0], acc[r]);
            acc[r] = fmaf(e0.y, w[1], acc[r]);
            acc[r] = fmaf(e0.z, w[2], acc[r]);
            acc[r] = fmaf(e0.w, w[3], acc[r]);
            acc[r] = fmaf(e1.x, w[4], acc[r]);
            acc[r] = fmaf(e1.y, w[5], acc[r]);
            acc[r] = fmaf(e1.z, w[6], acc[r]);
            acc[r] = fmaf(e1.w, w[7], acc[r]);
        }
    }
    if (ks == 1) {   // tail k = 144..146
        float w0 = Wp[144*CDIM], w1 = Wp[145*CDIM], w2 = Wp[146*CDIM];
        #pragma unroll
        for (int r = 0; r < 8; r++) {
            acc[r] = fmaf(En[r][144], w0, acc[r]);
            acc[r] = fmaf(En[r][145], w1, acc[r]);
            acc[r] = fmaf(En[r][146], w2, acc[r]);
        }
        #pragma unroll
        for (int r = 0; r < 8; r++) red[r][cl] = acc[r];
    }
    __syncthreads();
    if (ks == 0) {
        float pw0 = PEW[c], pw1 = PEW[CDIM + c], pw2 = PEW[2*CDIM + c];
        float pb  = PEB[c] + PFB[c];
        #pragma unroll
        for (int r = 0; r < 8; r++) {
            int s = r0 + r;
            float v = acc[r] + red[r][cl] + pb
                    + g_ctr[s*3+0]*pw0 + g_ctr[s*3+1]*pw1 + g_ctr[s*3+2]*pw2
                    + g_temb[(s/20)*CDIM + c];
            g_X[s*CDIM + c] = v;
        }
    }
}

// ---------------------------------------------------------------------------
// K4: Y1 = X @ o_w1 + o_b1 (640x512x256) + stat atomics.
// grid (80,2), block 256: 8 rows x 128 cols, split-K 2x256.
// ---------------------------------------------------------------------------
__global__ void k_gemm1(const float* __restrict__ W, const float* __restrict__ B)
{
    __shared__ float Xs[8][CDIM];      // 16 KB
    __shared__ float red[8][128];      // 4 KB
    int tid = threadIdx.x;
    int cl = tid & 127, ks = tid >> 7;
    int r0 = blockIdx.x * 8;
    int c  = blockIdx.y * 128 + cl;
    for (int idx = tid; idx < 8*128; idx += 256) {
        int r = idx >> 7, q = idx & 127;
        ((float4*)Xs[r])[q] = ((const float4*)(g_X + (r0+r)*CDIM))[q];
    }
    __syncthreads();
    int kbase = ks * 256;
    const float* Wp = W + (long)kbase * 256 + c;
    float acc[8];
    #pragma unroll
    for (int r = 0; r < 8; r++) acc[r] = 0.f;
    for (int k0 = 0; k0 < 256; k0 += 8) {
        float w[8];
        #pragma unroll
        for (int u = 0; u < 8; u++) w[u] = Wp[(long)(k0+u)*256];
        #pragma unroll
        for (int r = 0; r < 8; r++) {
            float4 e0 = *(const float4*)&Xs[r][kbase + k0];
            float4 e1 = *(const float4*)&Xs[r][kbase + k0 + 4];
            acc[r] = fmaf(e0.x, w[0], acc[r]);
            acc[r] = fmaf(e0.y, w[1], acc[r]);
            acc[r] = fmaf(e0.z, w[2], acc[r]);
            acc[r] = fmaf(e0.w, w[3], acc[r]);
            acc[r] = fmaf(e1.x, w[4], acc[r]);
            acc[r] = fmaf(e1.y, w[5], acc[r]);
            acc[r] = fmaf(e1.z, w[6], acc[r]);
            acc[r] = fmaf(e1.w, w[7], acc[r]);
        }
    }
    if (ks == 1) {
        #pragma unroll
        for (int r = 0; r < 8; r++) red[r][cl] = acc[r];
    }
    __syncthreads();
    if (ks == 0) {
        float bb = B[c];
        float s1 = 0.f, s2 = 0.f;
        #pragma unroll
        for (int r = 0; r < 8; r++) {
            float y = acc[r] + red[r][cl] + bb;
            g_Y1[(r0+r)*256 + c] = y;
            s1 += y; s2 += y*y;
        }
        atomicAdd(&g_stats[c], s1);
        atomicAdd(&g_stats[256 + c], s2);
    }
}

// ---------------------------------------------------------------------------
// K5: H1 = relu(bn1(Y1)) on load; Y2 = H1 @ o_w2 + o_b2 + stat atomics.
// grid (80), block 256: 8 rows x 128 cols, split-K 2x128.
// ---------------------------------------------------------------------------
__global__ void k_gemm2(const float* __restrict__ W, const float* __restrict__ B,
                        const float* __restrict__ G1, const float* __restrict__ B1)
{
    __shared__ float Hs[8][256];       // 8 KB
    __shared__ float red[8][128];
    __shared__ float sc[256], sb[256];
    int tid = threadIdx.x;
    {
        float m = g_stats[tid]       * (1.f/NSEG);
        float v = g_stats[256 + tid] * (1.f/NSEG) - m*m;
        float s = rsqrtf(v + 1e-5f) * G1[tid];
        sc[tid] = s; sb[tid] = B1[tid] - m*s;
    }
    __syncthreads();
    int r0 = blockIdx.x * 8;
    for (int idx = tid; idx < 8*256; idx += 256) {
        int r = idx >> 8, j = idx & 255;
        float y = g_Y1[(r0+r)*256 + j];
        Hs[r][j] = fmaxf(fmaf(y, sc[j], sb[j]), 0.f);
    }
    __syncthreads();
    int cl = tid & 127, ks = tid >> 7;
    int kbase = ks * 128;
    const float* Wp = W + (long)kbase * 128 + cl;
    float acc[8];
    #pragma unroll
    for (int r = 0; r < 8; r++) acc[r] = 0.f;
    for (int k0 = 0; k0 < 128; k0 += 8) {
        float w[8];
        #pragma unroll
        for (int u = 0; u < 8; u++) w[u] = Wp[(long)(k0+u)*128];
        #pragma unroll
        for (int r = 0; r < 8; r++) {
            float4 e0 = *(const float4*)&Hs[r][kbase + k0];
            float4 e1 = *(const float4*)&Hs[r][kbase + k0 + 4];
            acc[r] = fmaf(e0.x, w[0], acc[r]);
            acc[r] = fmaf(e0.y, w[1], acc[r]);
            acc[r] = fmaf(e0.z, w[2], acc[r]);
            acc[r] = fmaf(e0.w, w[3], acc[r]);
            acc[r] = fmaf(e1.x, w[4], acc[r]);
            acc[r] = fmaf(e1.y, w[5], acc[r]);
            acc[r] = fmaf(e1.z, w[6], acc[r]);
            acc[r] = fmaf(e1.w, w[7], acc[r]);
        }
    }
    if (ks == 1) {
        #pragma unroll
        for (int r = 0; r < 8; r++) red[r][cl] = acc[r];
    }
    __syncthreads();
    if (ks == 0) {
        float bb = B[cl];
        float s1 = 0.f, s2 = 0.f;
        #pragma unroll
        for (int r = 0; r < 8; r++) {
            float y = acc[r] + red[r][cl] + bb;
            g_Y2[(r0+r)*128 + cl] = y;
            s1 += y; s2 += y*y;
        }
        atomicAdd(&g_stats[512 + cl], s1);
        atomicAdd(&g_stats[640 + cl], s2);
    }
}

// ---------------------------------------------------------------------------
// K6: out = relu(bn2(Y2)) @ o_w3 + o_b3.  grid (80), block 256.
// ---------------------------------------------------------------------------
__global__ void k_out(const float* __restrict__ W3, const float* __restrict__ B3,
                      const float* __restrict__ G2, const float* __restrict__ B2c,
                      float* __restrict__ out)
{
    __shared__ float sc[128], sb[128];
    __shared__ float h[8][128];
    __shared__ float w3[128*7];
    __shared__ float b3[7];
    int tid = threadIdx.x;
    if (tid < 128) {
        float m = g_stats[512 + tid] * (1.f/NSEG);
        float v = g_stats[640 + tid] * (1.f/NSEG) - m*m;
        float s = rsqrtf(v + 1e-5f) * G2[tid];
        sc[tid] = s; sb[tid] = B2c[tid] - m*s;
    }
    for (int idx = tid; idx < 128*7; idx += 256) w3[idx] = W3[idx];
    if (tid < 7) b3[tid] = B3[tid];
    __syncthreads();
    int r0 = blockIdx.x * 8;
    for (int idx = tid; idx < 8*128; idx += 256) {
        int r = idx >> 7, j = idx & 127;
        float y = g_Y2[(r0+r)*128 + j];
        h[r][j] = fmaxf(fmaf(y, sc[j], sb[j]), 0.f);
    }
    __syncthreads();
    int wid = tid >> 5, lane = tid & 31;
    float hv[4];
    #pragma unroll
    for (int u = 0; u < 4; u++) hv[u] = h[wid][lane + u*32];
    #pragma unroll
    for (int j = 0; j < 7; j++) {
        float a = 0.f;
        #pragma unroll
        for (int u = 0; u < 4; u++) a = fmaf(hv[u], w3[(lane + u*32)*7 + j], a);
        #pragma unroll
        for (int o = 16; o; o >>= 1) a += __shfl_down_sync(0xffffffffu, a, o);
        if (lane == 0) out[(r0+wid)*7 + j] = a + b3[j];
    }
}

// ---------------------------------------------------------------------------
extern "C" void kernel_launch(void* const* d_in, const int* in_sizes, int n_in,
                              void* d_out, int out_size)
{
    const float* noise = (const float*)d_in[0];
    const int*   ts    = (const int*)  d_in[1];
    const float* pcs   = (const float*)d_in[2];
    const int*   blen  = (const int*)  d_in[4];
    const float* pew   = (const float*)d_in[5];
    const float* peb   = (const float*)d_in[6];
    const float* tw1   = (const float*)d_in[7];
    const float* tb1   = (const float*)d_in[8];
    const float* tw2   = (const float*)d_in[9];
    const float* tb2   = (const float*)d_in[10];
    const float* pfw   = (const float*)d_in[11];
    const float* pfb   = (const float*)d_in[12];
    const float* ow1   = (const float*)d_in[13];
    const float* ob1   = (const float*)d_in[14];
    const float* bn1g  = (const float*)d_in[15];
    const float* bn1b  = (const float*)d_in[16];
    const float* ow2   = (const float*)d_in[17];
    const float* ob2   = (const float*)d_in[18];
    const float* bn2g  = (const float*)d_in[19];
    const float* bn2b  = (const float*)d_in[20];
    const float* ow3   = (const float*)d_in[21];
    const float* ob3   = (const float*)d_in[22];
    float* out = (float*)d_out;

    k_pre       <<<NSEG + 4, 192>>>(noise, ts, pcs, blen);
    k_mlp512<0> <<<dim3(4,16), 256>>>(tw1, tb1);
    k_mlp512<1> <<<dim3(4,16), 256>>>(tw2, tb2);
    k_X         <<<dim3(80,4), 256>>>(pfw, pfb, pew, peb);
    k_gemm1     <<<dim3(80,2), 256>>>(ow1, ob1);
    k_gemm2     <<<80, 256>>>(ow2, ob2, bn1g, bn1b);
    k_out       <<<80, 256>>>(ow3, ob3, bn2g, bn2b, out);
}